// round 8
// baseline (speedup 1.0000x reference)
#include <cuda_runtime.h>

// GwcVolume: group-wise correlation cost volumes (lr + rl).
// Shapes (fixed): B=1, F=320, H=128, W=256, G=40, C=8, D=48.
//
// lr[g,d,h,w]  = (w>=d)   * (1/C) * sum_c L[gC+c,h,w] * R[gC+c,h,w-d]
// rl[g,d,h,w'] = (w'<W-d) * lr[g,d,h,w'+d]     (same values, shifted)
//
// One block per (g,h) row; 128 threads, each owning w0=2t, w0+1.
// Bins processed in packs of P=8 consecutive disparities: the 9-float
// R-window (5 aligned conflict-free LDS.64) serves all 16 dot products of
// the pack. Each dot product computed once, stored to lr (aligned STG.64)
// and to rl at the wrap index (w-d)&255 which also places the zero tails of
// both volumes branchlessly. Plain stores (no .cs) so L2 batches full-line
// write-backs. Scalar fallback path for non-arange bins.

constexpr int H = 128;
constexpr int W = 256;
constexpr int G = 40;
constexpr int C = 8;
constexpr int D = 48;
constexpr int T = 128;        // threads per block (V=2 outputs each)
constexpr int P = 8;          // bins per pack

__global__ __launch_bounds__(T, 8)
void gwc_volume_kernel(const float* __restrict__ L,
                       const float* __restrict__ R,
                       const int*   __restrict__ bins,
                       float*       __restrict__ out)
{
    const int h  = blockIdx.x;    // 0..H-1
    const int g  = blockIdx.y;    // 0..G-1
    const int t  = threadIdx.x;   // 0..T-1
    const int w0 = 2 * t;

    __shared__ __align__(16) float Rsh[C][W];   // 8 KB
    __shared__ int dsh[D];

    const long HW   = (long)H * W;
    const long base = (long)g * C * HW + (long)h * W + w0;

    // Stage inputs (coalesced LDG.64; each input byte read from DRAM once).
    // Fold 1/C into L: scaling by 0.125 is exact (power of two).
    float Lh[C][2];
#pragma unroll
    for (int c = 0; c < C; ++c) {
        const float2 lv = *(const float2*)(L + base + (long)c * HW);
        Lh[c][0] = lv.x * 0.125f;
        Lh[c][1] = lv.y * 0.125f;
        *(float2*)&Rsh[c][w0] = *(const float2*)(R + base + (long)c * HW);
    }
    if (t < D) dsh[t] = bins[t];
    __syncthreads();

    const float* __restrict__ RshF = &Rsh[0][0];
    float* __restrict__ lrq = out + (long)g * D * HW + (long)h * W;
    float* __restrict__ rlq = lrq + (long)G * D * HW;

#pragma unroll 1
    for (int i0 = 0; i0 < D; i0 += P, lrq += P * HW, rlq += P * HW) {
        const int d0 = dsh[i0];
        bool fast = ((d0 & 1) == 0);
#pragma unroll
        for (int p = 1; p < P; ++p) fast = fast && (dsh[i0 + p] == d0 + p);

        if (fast) {
            const int m = (w0 - d0) & (W - 1);   // even

            float v[P][2];
#pragma unroll
            for (int p = 0; p < P; ++p) { v[p][0] = 0.f; v[p][1] = 0.f; }

#pragma unroll
            for (int c = 0; c < C; ++c) {
                // Window r[0..9] = R[c][m-8 .. m+1] (wrapped). Wrapped entries
                // feed only masked-to-zero outputs (w < d).
                float r[10];
#pragma unroll
                for (int k = 0; k < 5; ++k) {
                    const float2 f =
                        *(const float2*)&RshF[c * W + ((m - 8 + 2 * k) & (W - 1))];
                    r[2 * k]     = f.x;
                    r[2 * k + 1] = f.y;
                }
#pragma unroll
                for (int p = 0; p < P; ++p) {
                    v[p][0] = fmaf(Lh[c][0], r[8 - p], v[p][0]);
                    v[p][1] = fmaf(Lh[c][1], r[9 - p], v[p][1]);
                }
            }

            // Stores: pointer-increment addressing, default cache policy so
            // L2 accumulates and writes back full 128B lines.
            float* lrp = lrq + w0;
            float* rlp = rlq;
#pragma unroll
            for (int p = 0; p < P; ++p) {
                const int d = d0 + p;
                const float a = (w0     >= d) ? v[p][0] : 0.f;
                const float b = (w0 + 1 >= d) ? v[p][1] : 0.f;

                *(float2*)lrp = make_float2(a, b);   // lr[g,i0+p,h,w0..w0+1]
                lrp += HW;

                const int pos = (m - p) & (W - 1);   // rl position of 'a'
                if ((p & 1) == 0) {                  // pos even -> aligned pair
                    *(float2*)(rlp + pos) = make_float2(a, b);
                } else {
                    rlp[pos] = a;
                    rlp[(pos + 1) & (W - 1)] = b;
                }
                rlp += HW;
            }
        } else {
            // General bins: per-bin scalar path (reference semantics).
#pragma unroll 1
            for (int q = 0; q < P; ++q) {
                const int d  = dsh[i0 + q];
                const int ia = (w0 - d) & (W - 1);
                const int ib = (w0 + 1 - d) & (W - 1);
                float a = 0.f, b = 0.f;
#pragma unroll
                for (int c = 0; c < C; ++c) {
                    a = fmaf(Lh[c][0], RshF[c * W + ia], a);
                    b = fmaf(Lh[c][1], RshF[c * W + ib], b);
                }
                a = (w0     >= d) ? a : 0.f;
                b = (w0 + 1 >= d) ? b : 0.f;
                const long off = (long)q * HW;
                lrq[off + w0]     = a;
                lrq[off + w0 + 1] = b;
                rlq[off + ia] = a;
                rlq[off + ib] = b;
            }
        }
    }
}

extern "C" void kernel_launch(void* const* d_in, const int* in_sizes, int n_in,
                              void* d_out, int out_size)
{
    const float* Lf   = (const float*)d_in[0];   // features_left  [1,320,128,256] f32
    const float* Rf   = (const float*)d_in[1];   // features_right [1,320,128,256] f32
    const int*   bins = (const int*)  d_in[2];   // [48] int32

    dim3 grid(H, G);
    gwc_volume_kernel<<<grid, T>>>(Lf, Rf, bins, (float*)d_out);
}

// round 9
// speedup vs baseline: 1.0121x; 1.0121x over previous
#include <cuda_runtime.h>

// GwcVolume: group-wise correlation cost volumes (lr + rl).
// Shapes (fixed): B=1, F=320, H=128, W=256, G=40, C=8, D=48.
//
// lr[g,d,h,w]  = (w>=d)   * (1/C) * sum_c L[gC+c,h,w] * R[gC+c,h,w-d]
// rl[g,d,h,w'] = (w'<W-d) * lr[g,d,h,w'+d]     (same values, shifted)
//
// One block per (g,h) row; 128 threads, each owning w0=2t, w0+1.
// Bins processed in packs of P=8 consecutive disparities: the 9-float
// R-window (5 aligned conflict-free LDS.64) serves all 16 dot products of
// the pack. Each dot product computed once, stored to lr (aligned STG.64)
// and to rl at the wrap index (w-d)&255, which also places the zero tails
// of both volumes branchlessly. Streaming (.cs) stores — measured faster
// than default policy (write-once data, no L2 reuse to harvest).
// Scalar fallback path for non-arange bins.

constexpr int H = 128;
constexpr int W = 256;
constexpr int G = 40;
constexpr int C = 8;
constexpr int D = 48;
constexpr int T = 128;        // threads per block (V=2 outputs each)
constexpr int P = 8;          // bins per pack

__global__ __launch_bounds__(T, 8)
void gwc_volume_kernel(const float* __restrict__ L,
                       const float* __restrict__ R,
                       const int*   __restrict__ bins,
                       float*       __restrict__ out)
{
    const int h  = blockIdx.x;    // 0..H-1
    const int g  = blockIdx.y;    // 0..G-1
    const int t  = threadIdx.x;   // 0..T-1
    const int w0 = 2 * t;

    __shared__ __align__(16) float Rsh[C][W];   // 8 KB
    __shared__ int dsh[D];

    const long HW   = (long)H * W;
    const long base = (long)g * C * HW + (long)h * W + w0;

    // Stage inputs (coalesced LDG.64; each input byte read from DRAM once).
    // Fold 1/C into L: scaling by 0.125 is exact (power of two).
    float Lh[C][2];
#pragma unroll
    for (int c = 0; c < C; ++c) {
        const float2 lv = *(const float2*)(L + base + (long)c * HW);
        Lh[c][0] = lv.x * 0.125f;
        Lh[c][1] = lv.y * 0.125f;
        *(float2*)&Rsh[c][w0] = *(const float2*)(R + base + (long)c * HW);
    }
    if (t < D) dsh[t] = bins[t];
    __syncthreads();

    const float* __restrict__ RshF = &Rsh[0][0];
    float* __restrict__ lrq = out + (long)g * D * HW + (long)h * W;
    float* __restrict__ rlq = lrq + (long)G * D * HW;

#pragma unroll 1
    for (int i0 = 0; i0 < D; i0 += P, lrq += P * HW, rlq += P * HW) {
        const int d0 = dsh[i0];
        bool fast = ((d0 & 1) == 0);
#pragma unroll
        for (int p = 1; p < P; ++p) fast = fast && (dsh[i0 + p] == d0 + p);

        if (fast) {
            const int m = (w0 - d0) & (W - 1);   // even

            float v[P][2];
#pragma unroll
            for (int p = 0; p < P; ++p) { v[p][0] = 0.f; v[p][1] = 0.f; }

#pragma unroll
            for (int c = 0; c < C; ++c) {
                // Window r[0..9] = R[c][m-8 .. m+1] (wrapped). Wrapped entries
                // feed only masked-to-zero outputs (w < d).
                float r[10];
#pragma unroll
                for (int k = 0; k < 5; ++k) {
                    const float2 f =
                        *(const float2*)&RshF[c * W + ((m - 8 + 2 * k) & (W - 1))];
                    r[2 * k]     = f.x;
                    r[2 * k + 1] = f.y;
                }
#pragma unroll
                for (int p = 0; p < P; ++p) {
                    v[p][0] = fmaf(Lh[c][0], r[8 - p], v[p][0]);
                    v[p][1] = fmaf(Lh[c][1], r[9 - p], v[p][1]);
                }
            }

            // Streaming stores, pointer-increment addressing (no per-bin
            // 64-bit multiplies).
            float* lrp = lrq + w0;
            float* rlp = rlq;
#pragma unroll
            for (int p = 0; p < P; ++p) {
                const int d = d0 + p;
                const float a = (w0     >= d) ? v[p][0] : 0.f;
                const float b = (w0 + 1 >= d) ? v[p][1] : 0.f;

                __stcs((float2*)lrp, make_float2(a, b));  // lr[g,i0+p,h,w0..w0+1]
                lrp += HW;

                const int pos = (m - p) & (W - 1);        // rl position of 'a'
                if ((p & 1) == 0) {                       // pos even -> aligned pair
                    __stcs((float2*)(rlp + pos), make_float2(a, b));
                } else {
                    __stcs(rlp + pos, a);
                    __stcs(rlp + ((pos + 1) & (W - 1)), b);
                }
                rlp += HW;
            }
        } else {
            // General bins: per-bin scalar path (reference semantics).
#pragma unroll 1
            for (int q = 0; q < P; ++q) {
                const int d  = dsh[i0 + q];
                const int ia = (w0 - d) & (W - 1);
                const int ib = (w0 + 1 - d) & (W - 1);
                float a = 0.f, b = 0.f;
#pragma unroll
                for (int c = 0; c < C; ++c) {
                    a = fmaf(Lh[c][0], RshF[c * W + ia], a);
                    b = fmaf(Lh[c][1], RshF[c * W + ib], b);
                }
                a = (w0     >= d) ? a : 0.f;
                b = (w0 + 1 >= d) ? b : 0.f;
                const long off = (long)q * HW;
                __stcs(lrq + off + w0,     a);
                __stcs(lrq + off + w0 + 1, b);
                __stcs(rlq + off + ia, a);
                __stcs(rlq + off + ib, b);
            }
        }
    }
}

extern "C" void kernel_launch(void* const* d_in, const int* in_sizes, int n_in,
                              void* d_out, int out_size)
{
    const float* Lf   = (const float*)d_in[0];   // features_left  [1,320,128,256] f32
    const float* Rf   = (const float*)d_in[1];   // features_right [1,320,128,256] f32
    const int*   bins = (const int*)  d_in[2];   // [48] int32

    dim3 grid(H, G);
    gwc_volume_kernel<<<grid, T>>>(Lf, Rf, bins, (float*)d_out);
}

// round 10
// speedup vs baseline: 1.0173x; 1.0051x over previous
#include <cuda_runtime.h>

// GwcVolume: group-wise correlation cost volumes (lr + rl).  FINAL (R6 config,
// measured fastest: 94.27us; DRAM-write roofline at ~5.9 TB/s achieved).
// Shapes (fixed): B=1, F=320, H=128, W=256, G=40, C=8, D=48.
//
// lr[g,d,h,w]  = (w>=d)   * (1/C) * sum_c L[gC+c,h,w] * R[gC+c,h,w-d]
// rl[g,d,h,w'] = (w'<W-d) * lr[g,d,h,w'+d]     (same values, shifted)
//
// One block per (g,h) row; 128 threads, each owning w0=2t, w0+1.
// Bins processed in packs of P=8 consecutive disparities: the 9-float
// R-window (5 aligned conflict-free LDS.64) serves all 16 dot products of
// the pack. Each dot product computed once, stored to lr (aligned STG.64)
// and to rl at the wrap index (w-d)&255, which also places the zero tails
// of both volumes branchlessly. Streaming (.cs) stores — measured faster
// than default policy (write-once data, no L2 reuse). Scalar fallback path
// preserves reference semantics for non-arange bins.

constexpr int H = 128;
constexpr int W = 256;
constexpr int G = 40;
constexpr int C = 8;
constexpr int D = 48;
constexpr int T = 128;        // threads per block (V=2 outputs each)
constexpr int P = 8;          // bins per pack

__global__ __launch_bounds__(T, 6)
void gwc_volume_kernel(const float* __restrict__ L,
                       const float* __restrict__ R,
                       const int*   __restrict__ bins,
                       float*       __restrict__ out)
{
    const int h  = blockIdx.x;    // 0..H-1
    const int g  = blockIdx.y;    // 0..G-1
    const int t  = threadIdx.x;   // 0..T-1
    const int w0 = 2 * t;

    __shared__ __align__(16) float Rsh[C][W];   // 8 KB
    __shared__ int dsh[D];

    const long HW   = (long)H * W;
    const long base = (long)g * C * HW + (long)h * W + w0;

    // Stage inputs (coalesced LDG.64; each input byte read from DRAM once).
    // Fold 1/C into L: scaling by 0.125 is exact (power of two).
    float Lh[C][2];
#pragma unroll
    for (int c = 0; c < C; ++c) {
        const float2 lv = *(const float2*)(L + base + (long)c * HW);
        Lh[c][0] = lv.x * 0.125f;
        Lh[c][1] = lv.y * 0.125f;
        *(float2*)&Rsh[c][w0] = *(const float2*)(R + base + (long)c * HW);
    }
    if (t < D) dsh[t] = bins[t];
    __syncthreads();

    const float* __restrict__ RshF = &Rsh[0][0];
    float* __restrict__ lrq = out + (long)g * D * HW + (long)h * W;
    float* __restrict__ rlq = lrq + (long)G * D * HW;

#pragma unroll 1
    for (int i0 = 0; i0 < D; i0 += P, lrq += P * HW, rlq += P * HW) {
        const int d0 = dsh[i0];
        bool fast = ((d0 & 1) == 0);
#pragma unroll
        for (int p = 1; p < P; ++p) fast = fast && (dsh[i0 + p] == d0 + p);

        if (fast) {
            const int m = (w0 - d0) & (W - 1);   // even

            float v[P][2];
#pragma unroll
            for (int p = 0; p < P; ++p) { v[p][0] = 0.f; v[p][1] = 0.f; }

#pragma unroll
            for (int c = 0; c < C; ++c) {
                // Window r[0..9] = R[c][m-8 .. m+1] (wrapped). Wrapped entries
                // feed only masked-to-zero outputs (w < d).
                float r[10];
#pragma unroll
                for (int k = 0; k < 5; ++k) {
                    const float2 f =
                        *(const float2*)&RshF[c * W + ((m - 8 + 2 * k) & (W - 1))];
                    r[2 * k]     = f.x;
                    r[2 * k + 1] = f.y;
                }
#pragma unroll
                for (int p = 0; p < P; ++p) {
                    v[p][0] = fmaf(Lh[c][0], r[8 - p], v[p][0]);
                    v[p][1] = fmaf(Lh[c][1], r[9 - p], v[p][1]);
                }
            }

#pragma unroll
            for (int p = 0; p < P; ++p) {
                const int d = d0 + p;
                const float a = (w0     >= d) ? v[p][0] : 0.f;
                const float b = (w0 + 1 >= d) ? v[p][1] : 0.f;

                __stcs((float2*)(lrq + (long)p * HW + w0), make_float2(a, b));

                const int pos = (m - p) & (W - 1);   // rl position of 'a'
                if ((p & 1) == 0) {                  // pos even -> aligned pair
                    __stcs((float2*)(rlq + (long)p * HW + pos), make_float2(a, b));
                } else {
                    __stcs(rlq + (long)p * HW + pos, a);
                    __stcs(rlq + (long)p * HW + ((pos + 1) & (W - 1)), b);
                }
            }
        } else {
            // General bins: per-bin scalar path (reference semantics).
#pragma unroll 1
            for (int q = 0; q < P; ++q) {
                const int d  = dsh[i0 + q];
                const int ia = (w0 - d) & (W - 1);
                const int ib = (w0 + 1 - d) & (W - 1);
                float a = 0.f, b = 0.f;
#pragma unroll
                for (int c = 0; c < C; ++c) {
                    a = fmaf(Lh[c][0], RshF[c * W + ia], a);
                    b = fmaf(Lh[c][1], RshF[c * W + ib], b);
                }
                a = (w0     >= d) ? a : 0.f;
                b = (w0 + 1 >= d) ? b : 0.f;
                const long off = (long)q * HW;
                __stcs(lrq + off + w0,     a);
                __stcs(lrq + off + w0 + 1, b);
                __stcs(rlq + off + ia, a);
                __stcs(rlq + off + ib, b);
            }
        }
    }
}

extern "C" void kernel_launch(void* const* d_in, const int* in_sizes, int n_in,
                              void* d_out, int out_size)
{
    const float* Lf   = (const float*)d_in[0];   // features_left  [1,320,128,256] f32
    const float* Rf   = (const float*)d_in[1];   // features_right [1,320,128,256] f32
    const int*   bins = (const int*)  d_in[2];   // [48] int32

    dim3 grid(H, G);
    gwc_volume_kernel<<<grid, T>>>(Lf, Rf, bins, (float*)d_out);
}

// round 11
// speedup vs baseline: 1.0176x; 1.0003x over previous
#include <cuda_runtime.h>

// GwcVolume: group-wise correlation cost volumes (lr + rl).
// Shapes (fixed): B=1, F=320, H=128, W=256, G=40, C=8, D=48.
//
// lr[g,d,h,w]  = (w>=d)   * (1/C) * sum_c L[gC+c,h,w] * R[gC+c,h,w-d]
// rl[g,d,h,w'] = (w'<W-d) * lr[g,d,h,w'+d]     (same values, shifted)
//
// R10: two h-rows per block (256 thr = 2 x 128). Each half-block runs the
// proven pack-of-8 window kernel for its row; the two halves write adjacent
// 1 KB rows of every output plane at the same time -> contiguous 2 KB DRAM
// write bursts (HBM page locality), attacking the write-efficiency binder.
// Inner loop identical to the measured-best R6/R9 kernel: 9-float R-window
// (5 aligned conflict-free LDS.64) serves 16 dot products per pack; each
// value computed once, stored to lr (aligned STG.64) and to rl at the wrap
// index (w-d)&255 which also places both zero tails branchlessly; streaming
// (.cs) stores (measured faster than default). Scalar fallback for
// non-arange bins.

constexpr int H = 128;
constexpr int W = 256;
constexpr int G = 40;
constexpr int C = 8;
constexpr int D = 48;
constexpr int RT = 128;       // threads per row (V=2 outputs each)
constexpr int T  = 2 * RT;    // 2 rows per block
constexpr int P  = 8;         // bins per pack

__global__ __launch_bounds__(T, 3)
void gwc_volume_kernel(const float* __restrict__ L,
                       const float* __restrict__ R,
                       const int*   __restrict__ bins,
                       float*       __restrict__ out)
{
    const int g  = blockIdx.y;          // 0..G-1
    const int ht = threadIdx.x / RT;    // 0..1 : row within block
    const int t  = threadIdx.x % RT;    // 0..RT-1
    const int h  = 2 * blockIdx.x + ht; // 0..H-1
    const int w0 = 2 * t;

    __shared__ __align__(16) float Rsh[2][C][W];   // 16 KB
    __shared__ int dsh[D];

    const long HW   = (long)H * W;
    const long base = (long)g * C * HW + (long)h * W + w0;

    // Stage inputs (coalesced LDG.64; each input byte read from DRAM once).
    // Fold 1/C into L: scaling by 0.125 is exact (power of two).
    float Lh[C][2];
#pragma unroll
    for (int c = 0; c < C; ++c) {
        const float2 lv = *(const float2*)(L + base + (long)c * HW);
        Lh[c][0] = lv.x * 0.125f;
        Lh[c][1] = lv.y * 0.125f;
        *(float2*)&Rsh[ht][c][w0] = *(const float2*)(R + base + (long)c * HW);
    }
    if (threadIdx.x < D) dsh[threadIdx.x] = bins[threadIdx.x];
    __syncthreads();

    const float* __restrict__ RshF = &Rsh[ht][0][0];
    float* __restrict__ lrq = out + (long)g * D * HW + (long)h * W;
    float* __restrict__ rlq = lrq + (long)G * D * HW;

#pragma unroll 1
    for (int i0 = 0; i0 < D; i0 += P, lrq += P * HW, rlq += P * HW) {
        const int d0 = dsh[i0];
        bool fast = ((d0 & 1) == 0);
#pragma unroll
        for (int p = 1; p < P; ++p) fast = fast && (dsh[i0 + p] == d0 + p);

        if (fast) {
            const int m = (w0 - d0) & (W - 1);   // even

            float v[P][2];
#pragma unroll
            for (int p = 0; p < P; ++p) { v[p][0] = 0.f; v[p][1] = 0.f; }

#pragma unroll
            for (int c = 0; c < C; ++c) {
                // Window r[0..9] = R[c][m-8 .. m+1] (wrapped). Wrapped entries
                // feed only masked-to-zero outputs (w < d).
                float r[10];
#pragma unroll
                for (int k = 0; k < 5; ++k) {
                    const float2 f =
                        *(const float2*)&RshF[c * W + ((m - 8 + 2 * k) & (W - 1))];
                    r[2 * k]     = f.x;
                    r[2 * k + 1] = f.y;
                }
#pragma unroll
                for (int p = 0; p < P; ++p) {
                    v[p][0] = fmaf(Lh[c][0], r[8 - p], v[p][0]);
                    v[p][1] = fmaf(Lh[c][1], r[9 - p], v[p][1]);
                }
            }

#pragma unroll
            for (int p = 0; p < P; ++p) {
                const int d = d0 + p;
                const float a = (w0     >= d) ? v[p][0] : 0.f;
                const float b = (w0 + 1 >= d) ? v[p][1] : 0.f;

                __stcs((float2*)(lrq + (long)p * HW + w0), make_float2(a, b));

                const int pos = (m - p) & (W - 1);   // rl position of 'a'
                if ((p & 1) == 0) {                  // pos even -> aligned pair
                    __stcs((float2*)(rlq + (long)p * HW + pos), make_float2(a, b));
                } else {
                    __stcs(rlq + (long)p * HW + pos, a);
                    __stcs(rlq + (long)p * HW + ((pos + 1) & (W - 1)), b);
                }
            }
        } else {
            // General bins: per-bin scalar path (reference semantics).
#pragma unroll 1
            for (int q = 0; q < P; ++q) {
                const int d  = dsh[i0 + q];
                const int ia = (w0 - d) & (W - 1);
                const int ib = (w0 + 1 - d) & (W - 1);
                float a = 0.f, b = 0.f;
#pragma unroll
                for (int c = 0; c < C; ++c) {
                    a = fmaf(Lh[c][0], RshF[c * W + ia], a);
                    b = fmaf(Lh[c][1], RshF[c * W + ib], b);
                }
                a = (w0     >= d) ? a : 0.f;
                b = (w0 + 1 >= d) ? b : 0.f;
                const long off = (long)q * HW;
                __stcs(lrq + off + w0,     a);
                __stcs(lrq + off + w0 + 1, b);
                __stcs(rlq + off + ia, a);
                __stcs(rlq + off + ib, b);
            }
        }
    }
}

extern "C" void kernel_launch(void* const* d_in, const int* in_sizes, int n_in,
                              void* d_out, int out_size)
{
    const float* Lf   = (const float*)d_in[0];   // features_left  [1,320,128,256] f32
    const float* Rf   = (const float*)d_in[1];   // features_right [1,320,128,256] f32
    const int*   bins = (const int*)  d_in[2];   // [48] int32

    dim3 grid(H / 2, G);
    gwc_volume_kernel<<<grid, T>>>(Lf, Rf, bins, (float*)d_out);
}

// round 12
// speedup vs baseline: 1.0180x; 1.0003x over previous
#include <cuda_runtime.h>

// GwcVolume: group-wise correlation cost volumes (lr + rl).
// FINAL ARTIFACT — converged at the HBM write-stream roofline
// (5.83 TB/s achieved; DRAM% invariant across occupancy/L1/issue/policy).
// Shapes (fixed): B=1, F=320, H=128, W=256, G=40, C=8, D=48.
//
// lr[g,d,h,w]  = (w>=d)   * (1/C) * sum_c L[gC+c,h,w] * R[gC+c,h,w-d]
// rl[g,d,h,w'] = (w'<W-d) * lr[g,d,h,w'+d]     (same values, shifted)
//
// Two h-rows per block (256 thr = 2 x 128); each half-block runs the proven
// pack-of-8 window kernel for its row, so every output plane receives
// contiguous 2 KB write bursts. Bins processed in packs of P=8 consecutive
// disparities: the 9-float R-window (5 aligned conflict-free LDS.64) serves
// all 16 dot products of a pack. Each value computed once, stored to lr
// (aligned STG.64) and to rl at the wrap index (w-d)&255, which also places
// the zero tails of both volumes branchlessly. Streaming (.cs) stores
// (measured faster than default: write-once data, no L2 reuse). Scalar
// fallback path preserves reference semantics for non-arange bins.

constexpr int H = 128;
constexpr int W = 256;
constexpr int G = 40;
constexpr int C = 8;
constexpr int D = 48;
constexpr int RT = 128;       // threads per row (V=2 outputs each)
constexpr int T  = 2 * RT;    // 2 rows per block
constexpr int P  = 8;         // bins per pack

__global__ __launch_bounds__(T, 3)
void gwc_volume_kernel(const float* __restrict__ L,
                       const float* __restrict__ R,
                       const int*   __restrict__ bins,
                       float*       __restrict__ out)
{
    const int g  = blockIdx.y;          // 0..G-1
    const int ht = threadIdx.x / RT;    // 0..1 : row within block
    const int t  = threadIdx.x % RT;    // 0..RT-1
    const int h  = 2 * blockIdx.x + ht; // 0..H-1
    const int w0 = 2 * t;

    __shared__ __align__(16) float Rsh[2][C][W];   // 16 KB
    __shared__ int dsh[D];

    const long HW   = (long)H * W;
    const long base = (long)g * C * HW + (long)h * W + w0;

    // Stage inputs (coalesced LDG.64; each input byte read from DRAM once).
    // Fold 1/C into L: scaling by 0.125 is exact (power of two).
    float Lh[C][2];
#pragma unroll
    for (int c = 0; c < C; ++c) {
        const float2 lv = *(const float2*)(L + base + (long)c * HW);
        Lh[c][0] = lv.x * 0.125f;
        Lh[c][1] = lv.y * 0.125f;
        *(float2*)&Rsh[ht][c][w0] = *(const float2*)(R + base + (long)c * HW);
    }
    if (threadIdx.x < D) dsh[threadIdx.x] = bins[threadIdx.x];
    __syncthreads();

    const float* __restrict__ RshF = &Rsh[ht][0][0];
    float* __restrict__ lrq = out + (long)g * D * HW + (long)h * W;
    float* __restrict__ rlq = lrq + (long)G * D * HW;

#pragma unroll 1
    for (int i0 = 0; i0 < D; i0 += P, lrq += P * HW, rlq += P * HW) {
        const int d0 = dsh[i0];
        bool fast = ((d0 & 1) == 0);
#pragma unroll
        for (int p = 1; p < P; ++p) fast = fast && (dsh[i0 + p] == d0 + p);

        if (fast) {
            const int m = (w0 - d0) & (W - 1);   // even

            float v[P][2];
#pragma unroll
            for (int p = 0; p < P; ++p) { v[p][0] = 0.f; v[p][1] = 0.f; }

#pragma unroll
            for (int c = 0; c < C; ++c) {
                // Window r[0..9] = R[c][m-8 .. m+1] (wrapped). Wrapped entries
                // feed only masked-to-zero outputs (w < d).
                float r[10];
#pragma unroll
                for (int k = 0; k < 5; ++k) {
                    const float2 f =
                        *(const float2*)&RshF[c * W + ((m - 8 + 2 * k) & (W - 1))];
                    r[2 * k]     = f.x;
                    r[2 * k + 1] = f.y;
                }
#pragma unroll
                for (int p = 0; p < P; ++p) {
                    v[p][0] = fmaf(Lh[c][0], r[8 - p], v[p][0]);
                    v[p][1] = fmaf(Lh[c][1], r[9 - p], v[p][1]);
                }
            }

#pragma unroll
            for (int p = 0; p < P; ++p) {
                const int d = d0 + p;
                const float a = (w0     >= d) ? v[p][0] : 0.f;
                const float b = (w0 + 1 >= d) ? v[p][1] : 0.f;

                __stcs((float2*)(lrq + (long)p * HW + w0), make_float2(a, b));

                const int pos = (m - p) & (W - 1);   // rl position of 'a'
                if ((p & 1) == 0) {                  // pos even -> aligned pair
                    __stcs((float2*)(rlq + (long)p * HW + pos), make_float2(a, b));
                } else {
                    __stcs(rlq + (long)p * HW + pos, a);
                    __stcs(rlq + (long)p * HW + ((pos + 1) & (W - 1)), b);
                }
            }
        } else {
            // General bins: per-bin scalar path (reference semantics).
#pragma unroll 1
            for (int q = 0; q < P; ++q) {
                const int d  = dsh[i0 + q];
                const int ia = (w0 - d) & (W - 1);
                const int ib = (w0 + 1 - d) & (W - 1);
                float a = 0.f, b = 0.f;
#pragma unroll
                for (int c = 0; c < C; ++c) {
                    a = fmaf(Lh[c][0], RshF[c * W + ia], a);
                    b = fmaf(Lh[c][1], RshF[c * W + ib], b);
                }
                a = (w0     >= d) ? a : 0.f;
                b = (w0 + 1 >= d) ? b : 0.f;
                const long off = (long)q * HW;
                __stcs(lrq + off + w0,     a);
                __stcs(lrq + off + w0 + 1, b);
                __stcs(rlq + off + ia, a);
                __stcs(rlq + off + ib, b);
            }
        }
    }
}

extern "C" void kernel_launch(void* const* d_in, const int* in_sizes, int n_in,
                              void* d_out, int out_size)
{
    const float* Lf   = (const float*)d_in[0];   // features_left  [1,320,128,256] f32
    const float* Rf   = (const float*)d_in[1];   // features_right [1,320,128,256] f32
    const int*   bins = (const int*)  d_in[2];   // [48] int32

    dim3 grid(H / 2, G);
    gwc_volume_kernel<<<grid, T>>>(Lf, Rf, bins, (float*)d_out);
}